// round 1
// baseline (speedup 1.0000x reference)
#include <cuda_runtime.h>
#include <cuda_bf16.h>

// BackwardRPM: 16384 independent 200-step solves.
//   per step: h = tanh(u@W1 + b1) (64,), grad6 = C@h + d - s, u = clip(u - 0.01*grad6)
// with A = R[:, :6]^T R (6x40), C = A @ W2^T (6x64), d = A@b2, s = A@spec.
//
// Parallelization: 8 lanes per sample (each owns 8 hidden units, weights in
// registers), grad reduced with shfl.bfly within the 8-lane group.

#define STEPS 200
#define LR 0.01f
#define BATCH 16384
#define HID 64
#define PROJ 8
#define NSPEC 40

// Precomputed small matrices (device scratch; no allocation allowed).
__device__ float g_A[6 * NSPEC];   // A = R6^T R
__device__ float g_C[6 * HID];     // C = A W2^T  (C[i*64+j])
__device__ float g_d[6];           // d = A b2

__global__ void precompute_kernel(const float* __restrict__ W2,
                                  const float* __restrict__ b2,
                                  const float* __restrict__ R) {
    __shared__ float sA[6 * NSPEC];
    int tid = threadIdx.x;

    // A[i][k] = sum_p R[p*40+i] * R[p*40+k], i<6, k<40
    for (int t = tid; t < 6 * NSPEC; t += blockDim.x) {
        int i = t / NSPEC;
        int k = t % NSPEC;
        float acc = 0.0f;
#pragma unroll
        for (int p = 0; p < PROJ; ++p)
            acc = fmaf(R[p * NSPEC + i], R[p * NSPEC + k], acc);
        sA[t] = acc;
        g_A[t] = acc;
    }
    __syncthreads();

    // C[i][j] = sum_k A[i][k] * W2[j*40+k]
    for (int t = tid; t < 6 * HID; t += blockDim.x) {
        int i = t / HID;
        int j = t % HID;
        float acc = 0.0f;
#pragma unroll
        for (int k = 0; k < NSPEC; ++k)
            acc = fmaf(sA[i * NSPEC + k], W2[j * NSPEC + k], acc);
        g_C[t] = acc;
    }

    // d[i] = sum_k A[i][k] * b2[k]
    if (tid < 6) {
        float acc = 0.0f;
#pragma unroll
        for (int k = 0; k < NSPEC; ++k)
            acc = fmaf(sA[tid * NSPEC + k], b2[k], acc);
        g_d[tid] = acc;
    }
}

__device__ __forceinline__ float tanh_fast(float v) {
    // tanh(v) = 1 - 2/(exp(2v)+1); saturates correctly at +/-1.
    float e = __expf(2.0f * v);
    return 1.0f - __fdividef(2.0f, e + 1.0f);
}

__global__ void __launch_bounds__(128)
solve_kernel(const float* __restrict__ spectrum,
             const float* __restrict__ W1,
             const float* __restrict__ b1,
             float* __restrict__ out) {
    const int gtid = blockIdx.x * blockDim.x + threadIdx.x;
    const int sample = gtid >> 3;       // 8 lanes per sample
    const int sub = gtid & 7;           // which 8-unit slice of hidden dim
    if (sample >= BATCH) return;

    // Load this lane's weight slice into registers (loop-invariant).
    float w1r[6][8];   // W1[i][j], j = sub + 8*jj
    float cr[6][8];    // C[i][j]
    float b1r[8];
#pragma unroll
    for (int jj = 0; jj < 8; ++jj) {
        int j = sub + 8 * jj;
        b1r[jj] = __ldg(&b1[j]);
#pragma unroll
        for (int i = 0; i < 6; ++i) {
            w1r[i][jj] = __ldg(&W1[i * HID + j]);
            cr[i][jj]  = g_C[i * HID + j];
        }
    }

    // base[i] = d[i] - (A @ spec)[i]
    const float* sp = spectrum + sample * NSPEC;
    float base[6];
#pragma unroll
    for (int i = 0; i < 6; ++i) {
        float acc = 0.0f;
#pragma unroll
        for (int k = 0; k < NSPEC; ++k)
            acc = fmaf(g_A[i * NSPEC + k], __ldg(&sp[k]), acc);
        base[i] = g_d[i] - acc;
    }

    float u[6];
#pragma unroll
    for (int i = 0; i < 6; ++i) u[i] = 0.5f;

#pragma unroll 1
    for (int t = 0; t < STEPS; ++t) {
        float grad[6];
#pragma unroll
        for (int i = 0; i < 6; ++i) grad[i] = base[i];

#pragma unroll
        for (int jj = 0; jj < 8; ++jj) {
            float v = b1r[jj];
#pragma unroll
            for (int i = 0; i < 6; ++i) v = fmaf(u[i], w1r[i][jj], v);
            float h = tanh_fast(v);
#pragma unroll
            for (int i = 0; i < 6; ++i) grad[i] = fmaf(h, cr[i][jj], grad[i]);
        }

        // Butterfly reduce within the 8-lane group (xor 1,2,4 never crosses
        // an 8-lane boundary). base[] is identical across the group, so it is
        // added 8x — compensate by scaling contributions: instead, reduce only
        // the per-lane partial (grad - base) ... handled below by subtracting
        // 7*base after the reduction equivalently. Simpler: reduce partials.
        float part[6];
#pragma unroll
        for (int i = 0; i < 6; ++i) part[i] = grad[i] - base[i];
#pragma unroll
        for (int d = 1; d < 8; d <<= 1) {
#pragma unroll
            for (int i = 0; i < 6; ++i)
                part[i] += __shfl_xor_sync(0xffffffffu, part[i], d);
        }

#pragma unroll
        for (int i = 0; i < 6; ++i) {
            float g = part[i] + base[i];
            float un = fmaf(-LR, g, u[i]);
            u[i] = fminf(1.0f, fmaxf(0.0f, un));
        }
    }

    if (sub == 0) {
#pragma unroll
        for (int i = 0; i < 6; ++i)
            out[sample * 6 + i] = u[i];
    }
}

extern "C" void kernel_launch(void* const* d_in, const int* in_sizes, int n_in,
                              void* d_out, int out_size) {
    // metadata order: spectrum, W1, b1, W2, b2, R
    const float* spectrum = (const float*)d_in[0];
    const float* W1 = (const float*)d_in[1];
    const float* b1 = (const float*)d_in[2];
    const float* W2 = (const float*)d_in[3];
    const float* b2 = (const float*)d_in[4];
    const float* R  = (const float*)d_in[5];
    float* out = (float*)d_out;

    precompute_kernel<<<1, 256>>>(W2, b2, R);

    const int threads = 128;
    const int total = BATCH * 8;
    solve_kernel<<<total / threads, threads>>>(spectrum, W1, b1, out);
}

// round 3
// speedup vs baseline: 1.3623x; 1.3623x over previous
#include <cuda_runtime.h>
#include <cuda_bf16.h>

// BackwardRPM: 16384 independent 200-step solves.
//   per step: h = tanh(u@W1 + b1) (64,), grad6 = C@h + d - s, u = clip(u - 0.01*grad6)
// with A = R[:, :6]^T R (6x40), C = A W2^T (6x64), d = A@b2, s = A@spec.
//
// R2: fma.rn.f32x2 packing of hidden-unit pairs (halves fma-pipe slots for the
// two dominant loops) + MUFU.TANH (tanh.approx.f32, 1 MUFU vs 2 MUFU + prep).

#define STEPS 200
#define LR 0.01f
#define BATCH 16384
#define HID 64
#define PROJ 8
#define NSPEC 40

typedef unsigned long long u64x;

__device__ float g_A[6 * NSPEC];   // A = R6^T R
__device__ float g_C[6 * HID];     // C = A W2^T
__device__ float g_d[6];           // d = A b2

__global__ void precompute_kernel(const float* __restrict__ W2,
                                  const float* __restrict__ b2,
                                  const float* __restrict__ R) {
    __shared__ float sA[6 * NSPEC];
    int tid = threadIdx.x;

    for (int t = tid; t < 6 * NSPEC; t += blockDim.x) {
        int i = t / NSPEC, k = t % NSPEC;
        float acc = 0.0f;
#pragma unroll
        for (int p = 0; p < PROJ; ++p)
            acc = fmaf(R[p * NSPEC + i], R[p * NSPEC + k], acc);
        sA[t] = acc;
        g_A[t] = acc;
    }
    __syncthreads();

    for (int t = tid; t < 6 * HID; t += blockDim.x) {
        int i = t / HID, j = t % HID;
        float acc = 0.0f;
#pragma unroll
        for (int k = 0; k < NSPEC; ++k)
            acc = fmaf(sA[i * NSPEC + k], W2[j * NSPEC + k], acc);
        g_C[t] = acc;
    }

    if (tid < 6) {
        float acc = 0.0f;
#pragma unroll
        for (int k = 0; k < NSPEC; ++k)
            acc = fmaf(sA[tid * NSPEC + k], b2[k], acc);
        g_d[tid] = acc;
    }
}

// ---- f32x2 helpers (ptxas will not auto-fuse these; PTX-only path) ----
__device__ __forceinline__ u64x pack2(float lo, float hi) {
    u64x r; asm("mov.b64 %0, {%1, %2};" : "=l"(r) : "f"(lo), "f"(hi)); return r;
}
__device__ __forceinline__ void unpack2(u64x v, float& lo, float& hi) {
    asm("mov.b64 {%0, %1}, %2;" : "=f"(lo), "=f"(hi) : "l"(v));
}
__device__ __forceinline__ u64x fma2(u64x a, u64x b, u64x c) {
    u64x d; asm("fma.rn.f32x2 %0, %1, %2, %3;" : "=l"(d) : "l"(a), "l"(b), "l"(c)); return d;
}
__device__ __forceinline__ u64x add2(u64x a, u64x b) {
    u64x d; asm("add.rn.f32x2 %0, %1, %2;" : "=l"(d) : "l"(a), "l"(b)); return d;
}
__device__ __forceinline__ float tanh_fast(float x) {
    float y; asm("tanh.approx.f32 %0, %1;" : "=f"(y) : "f"(x)); return y;
}

__global__ void __launch_bounds__(128)
solve_kernel(const float* __restrict__ spectrum,
             const float* __restrict__ W1,
             const float* __restrict__ b1,
             float* __restrict__ out) {
    const int gtid = blockIdx.x * blockDim.x + threadIdx.x;
    const int sample = gtid >> 3;       // 8 lanes per sample
    const int sub = gtid & 7;           // hidden-dim slice
    if (sample >= BATCH) return;

    // Weight pairs in registers: pair p covers j0 = sub+16p and j1 = sub+16p+8.
    u64x w1p[6][4];
    u64x cp[6][4];
    u64x b1p[4];
#pragma unroll
    for (int p = 0; p < 4; ++p) {
        int j0 = sub + 16 * p;
        int j1 = j0 + 8;
        b1p[p] = pack2(__ldg(&b1[j0]), __ldg(&b1[j1]));
#pragma unroll
        for (int i = 0; i < 6; ++i) {
            w1p[i][p] = pack2(__ldg(&W1[i * HID + j0]), __ldg(&W1[i * HID + j1]));
            cp[i][p]  = pack2(g_C[i * HID + j0], g_C[i * HID + j1]);
        }
    }

    // base[i] = d[i] - (A @ spec)[i]
    const float* sp = spectrum + sample * NSPEC;
    float base[6];
#pragma unroll
    for (int i = 0; i < 6; ++i) {
        float acc = 0.0f;
#pragma unroll
        for (int k = 0; k < NSPEC; ++k)
            acc = fmaf(g_A[i * NSPEC + k], __ldg(&sp[k]), acc);
        base[i] = g_d[i] - acc;
    }

    float u[6];
#pragma unroll
    for (int i = 0; i < 6; ++i) u[i] = 0.5f;

#pragma unroll 1
    for (int t = 0; t < STEPS; ++t) {
        u64x ud[6];
#pragma unroll
        for (int i = 0; i < 6; ++i) ud[i] = pack2(u[i], u[i]);

        u64x g2[6];
#pragma unroll
        for (int i = 0; i < 6; ++i) g2[i] = 0ull;

#pragma unroll
        for (int p = 0; p < 4; ++p) {
            u64x v = b1p[p];
#pragma unroll
            for (int i = 0; i < 6; ++i) v = fma2(ud[i], w1p[i][p], v);
            float v0, v1;
            unpack2(v, v0, v1);
            u64x hp = pack2(tanh_fast(v0), tanh_fast(v1));
#pragma unroll
            for (int i = 0; i < 6; ++i) g2[i] = fma2(hp, cp[i][p], g2[i]);
        }

        // collapse jj-pairs -> 6 scalars
        float gr[6];
#pragma unroll
        for (int i = 0; i < 6; ++i) {
            float a, b;
            unpack2(g2[i], a, b);
            gr[i] = a + b;
        }

        // pack 6 scalars into 3 f32x2 for the butterfly reduction
        u64x r0 = pack2(gr[0], gr[1]);
        u64x r1 = pack2(gr[2], gr[3]);
        u64x r2 = pack2(gr[4], gr[5]);
#pragma unroll
        for (int d = 1; d < 8; d <<= 1) {
            r0 = add2(r0, __shfl_xor_sync(0xffffffffu, r0, d));
            r1 = add2(r1, __shfl_xor_sync(0xffffffffu, r1, d));
            r2 = add2(r2, __shfl_xor_sync(0xffffffffu, r2, d));
        }
        unpack2(r0, gr[0], gr[1]);
        unpack2(r1, gr[2], gr[3]);
        unpack2(r2, gr[4], gr[5]);

#pragma unroll
        for (int i = 0; i < 6; ++i) {
            float g = gr[i] + base[i];
            float un = fmaf(-LR, g, u[i]);
            u[i] = fminf(1.0f, fmaxf(0.0f, un));
        }
    }

    if (sub == 0) {
#pragma unroll
        for (int i = 0; i < 6; ++i)
            out[sample * 6 + i] = u[i];
    }
}

extern "C" void kernel_launch(void* const* d_in, const int* in_sizes, int n_in,
                              void* d_out, int out_size) {
    // metadata order: spectrum, W1, b1, W2, b2, R
    const float* spectrum = (const float*)d_in[0];
    const float* W1 = (const float*)d_in[1];
    const float* b1 = (const float*)d_in[2];
    const float* W2 = (const float*)d_in[3];
    const float* b2 = (const float*)d_in[4];
    const float* R  = (const float*)d_in[5];
    float* out = (float*)d_out;

    precompute_kernel<<<1, 256>>>(W2, b2, R);

    const int threads = 128;
    const int total = BATCH * 8;
    solve_kernel<<<total / threads, threads>>>(spectrum, W1, b1, out);
}